// round 3
// baseline (speedup 1.0000x reference)
#include <cuda_runtime.h>
#include <cuda_bf16.h>
#include <float.h>

// Problem constants
#define B   4
#define L   4096
#define HD  512
#define H   8
#define D   64
#define S   45
#define U   45
#define BL  (B * L)            // 16384
#define BH  (B * H)            // 32
#define KCH 8                  // K-split chunks for PV GEMM (512 l's each)

// ---------------- device scratch (static; no runtime allocation) ----------------
__device__ float g_Q[BL * HD];
__device__ float g_K[BL * HD];
__device__ float g_V[BL * HD];
__device__ float g_context[BL * HD];
__device__ float g_M[BH * L];
__device__ int   g_topidx[BH * U];
__device__ float g_scores[BH * U * L];      // reused in-place as attn
__device__ float g_vmean[BH * D];
__device__ float g_ctxpart[BH * KCH * U * D];
__device__ float g_ctxsel[BH * U * D];

// ---------------- GEMM: C[M=16384,512] = A[16384,512] @ W[512,512] ----------------
// 128x128 tile, BK=8, 256 threads, 8x8 per thread.
__global__ __launch_bounds__(256) void gemm128(const float* __restrict__ A,
                                               const float* __restrict__ W,
                                               float* __restrict__ C) {
    __shared__ float As[8][136];   // transposed A tile, padded (136*4 % 16 == 0)
    __shared__ float Bs[8][128];

    int tid = threadIdx.x;
    int bm = blockIdx.y * 128;
    int bn = blockIdx.x * 128;
    int tx = tid & 15;
    int ty = tid >> 4;

    float acc[8][8];
#pragma unroll
    for (int i = 0; i < 8; i++)
#pragma unroll
        for (int j = 0; j < 8; j++) acc[i][j] = 0.0f;

    int aRow = bm + (tid >> 1);        // 0..127
    int aCol = (tid & 1) * 4;          // 0 or 4
    int bRow = tid >> 5;               // 0..7
    int bCol = bn + (tid & 31) * 4;

    for (int k0 = 0; k0 < HD; k0 += 8) {
        float4 a = *(const float4*)&A[(size_t)aRow * HD + k0 + aCol];
        int r = tid >> 1;
        As[aCol + 0][r] = a.x;
        As[aCol + 1][r] = a.y;
        As[aCol + 2][r] = a.z;
        As[aCol + 3][r] = a.w;
        *(float4*)&Bs[bRow][(tid & 31) * 4] =
            *(const float4*)&W[(size_t)(k0 + bRow) * HD + bCol];
        __syncthreads();

#pragma unroll
        for (int kk = 0; kk < 8; kk++) {
            float4 a0 = *(float4*)&As[kk][ty * 4];
            float4 a1 = *(float4*)&As[kk][64 + ty * 4];
            float4 b0 = *(float4*)&Bs[kk][tx * 4];
            float4 b1 = *(float4*)&Bs[kk][64 + tx * 4];
            float ar[8] = {a0.x, a0.y, a0.z, a0.w, a1.x, a1.y, a1.z, a1.w};
            float br[8] = {b0.x, b0.y, b0.z, b0.w, b1.x, b1.y, b1.z, b1.w};
#pragma unroll
            for (int i = 0; i < 8; i++)
#pragma unroll
                for (int j = 0; j < 8; j++) acc[i][j] += ar[i] * br[j];
        }
        __syncthreads();
    }

#pragma unroll
    for (int i = 0; i < 8; i++) {
        int row = bm + ((i < 4) ? (ty * 4 + i) : (64 + ty * 4 + i - 4));
        float4 o0 = {acc[i][0], acc[i][1], acc[i][2], acc[i][3]};
        float4 o1 = {acc[i][4], acc[i][5], acc[i][6], acc[i][7]};
        *(float4*)&C[(size_t)row * HD + bn + tx * 4] = o0;
        *(float4*)&C[(size_t)row * HD + bn + 64 + tx * 4] = o1;
    }
}

// ---------------- v mean over L per (b,h,d) ----------------
__global__ __launch_bounds__(256) void vmean_kernel() {
    int bh = blockIdx.x;               // 0..31
    int b = bh >> 3, h = bh & 7;
    int t = threadIdx.x;
    int d = t & 63, part = t >> 6;     // 4 partitions over L
    const float* base = g_V + (size_t)b * L * HD + h * D + d;
    float s = 0.0f;
    for (int l = part; l < L; l += 4) s += base[(size_t)l * HD];
    __shared__ float sm[256];
    sm[t] = s;
    __syncthreads();
    if (t < 64) {
        float tot = sm[t] + sm[t + 64] + sm[t + 128] + sm[t + 192];
        g_vmean[bh * D + t] = tot * (1.0f / (float)L);
    }
}

// ---------------- M[b,h,l] = max_s(qk) - mean_s(qk) ----------------
// One warp per (b,l,h): 16384 blocks x 8 warps.
__global__ __launch_bounds__(256) void compute_M_kernel(const int* __restrict__ idx) {
    int bl = blockIdx.x;               // 0..16383
    int b = bl >> 12;
    int l = bl & (L - 1);
    int h = threadIdx.x >> 5;
    int lane = threadIdx.x & 31;

    const float* qrow = g_Q + (size_t)bl * HD + h * D;
    float q0 = qrow[lane];
    float q1 = qrow[lane + 32];

    float mx = -FLT_MAX, sum = 0.0f;
#pragma unroll 1
    for (int s = 0; s < S; s++) {
        int j = idx[l * S + s];
        const float* krow = g_K + ((size_t)b * L + j) * HD + h * D;
        float p = q0 * krow[lane] + q1 * krow[lane + 32];
#pragma unroll
        for (int o = 16; o; o >>= 1) p += __shfl_xor_sync(0xffffffffu, p, o);
        mx = fmaxf(mx, p);
        sum += p;
    }
    if (lane == 0)
        g_M[((size_t)b * H + h) * L + l] = mx - sum * (1.0f / (float)S);
}

// ---------------- top-45 per (b,h) with lowest-index tie-break ----------------
__global__ __launch_bounds__(256) void topk_kernel() {
    int bh = blockIdx.x;
    __shared__ float sv[L];
    __shared__ float rv[256];
    __shared__ int   ri[256];
    int t = threadIdx.x;
    const float* Mrow = g_M + (size_t)bh * L;
    for (int i = t; i < L; i += 256) sv[i] = Mrow[i];
    __syncthreads();
    for (int u = 0; u < U; u++) {
        float best = -FLT_MAX;
        int bi = L;
        for (int i = t; i < L; i += 256) {
            float v = sv[i];
            if (v > best) { best = v; bi = i; }   // ascending scan keeps lowest idx on ties
        }
        rv[t] = best; ri[t] = bi;
        __syncthreads();
        for (int s = 128; s; s >>= 1) {
            if (t < s) {
                if (rv[t + s] > rv[t] || (rv[t + s] == rv[t] && ri[t + s] < ri[t])) {
                    rv[t] = rv[t + s]; ri[t] = ri[t + s];
                }
            }
            __syncthreads();
        }
        if (t == 0) {
            g_topidx[bh * U + u] = ri[0];
            sv[ri[0]] = -FLT_MAX;
        }
        __syncthreads();
    }
}

// ---------------- scores[bh,u,l] = (Qr . k_l) * 1/8 ----------------
// grid (32 l-chunks of 128, 32 bh), 256 threads.
__global__ __launch_bounds__(256) void scores_kernel() {
    int bh = blockIdx.y;
    int b = bh >> 3, h = bh & 7;
    int l0 = blockIdx.x * 128;
    __shared__ float Qs[U][65];
    __shared__ float Ks[128][65];
    int t = threadIdx.x;

    for (int i = t; i < U * D; i += 256) {
        int u = i >> 6, d = i & 63;
        int li = g_topidx[bh * U + u];
        Qs[u][d] = g_Q[((size_t)b * L + li) * HD + h * D + d];
    }
    for (int i = t; i < 128 * D; i += 256) {
        int r = i >> 6, d = i & 63;
        Ks[r][d] = g_K[((size_t)b * L + l0 + r) * HD + h * D + d];
    }
    __syncthreads();

    for (int i = t; i < U * 128; i += 256) {
        int u = i >> 7, l = i & 127;
        float acc = 0.0f;
#pragma unroll
        for (int d = 0; d < D; d++) acc += Qs[u][d] * Ks[l][d];
        g_scores[((size_t)bh * U + u) * L + l0 + l] = acc * 0.125f;  // 1/sqrt(64)
    }
}

// ---------------- softmax over L per (bh,u) row; in place ----------------
__global__ __launch_bounds__(256) void softmax_kernel() {
    size_t row = blockIdx.x;                  // 0..1439
    float* p = g_scores + row * L;
    __shared__ float red[256];
    int t = threadIdx.x;

    float mx = -FLT_MAX;
    for (int i = t; i < L; i += 256) mx = fmaxf(mx, p[i]);
    red[t] = mx;
    __syncthreads();
    for (int s = 128; s; s >>= 1) { if (t < s) red[t] = fmaxf(red[t], red[t + s]); __syncthreads(); }
    mx = red[0];
    __syncthreads();

    float sum = 0.0f;
    for (int i = t; i < L; i += 256) {
        float e = __expf(p[i] - mx);
        p[i] = e;
        sum += e;
    }
    red[t] = sum;
    __syncthreads();
    for (int s = 128; s; s >>= 1) { if (t < s) red[t] += red[t + s]; __syncthreads(); }
    float inv = 1.0f / red[0];
    __syncthreads();
    for (int i = t; i < L; i += 256) p[i] *= inv;
}

// ---------------- PV partial: ctxpart[bh,kc,u,d] over 512 l's ----------------
// grid (KCH, 32 bh), 320 threads. Each thread owns (d, ugrp) and 9 u's.
__global__ __launch_bounds__(320) void ctx_partial_kernel() {
    int kc = blockIdx.x, bh = blockIdx.y;
    int b = bh >> 3, h = bh & 7;
    __shared__ float As[U][65];
    __shared__ float Vs[64][65];
    int t = threadIdx.x;
    int d = t & 63, ug = t >> 6;      // ug in 0..4

    float acc[9];
#pragma unroll
    for (int r = 0; r < 9; r++) acc[r] = 0.0f;

    int lbase = kc * (L / KCH);
    for (int lt = 0; lt < L / KCH; lt += 64) {
        for (int i = t; i < 64 * 64; i += 320) {
            int r = i >> 6, dd = i & 63;
            Vs[r][dd] = g_V[((size_t)b * L + lbase + lt + r) * HD + h * D + dd];
        }
        for (int i = t; i < U * 64; i += 320) {
            int u = i >> 6, ll = i & 63;
            As[u][ll] = g_scores[((size_t)bh * U + u) * L + lbase + lt + ll];
        }
        __syncthreads();
#pragma unroll 8
        for (int ll = 0; ll < 64; ll++) {
            float vv = Vs[ll][d];
#pragma unroll
            for (int r = 0; r < 9; r++) acc[r] += As[ug + 5 * r][ll] * vv;
        }
        __syncthreads();
    }
#pragma unroll
    for (int r = 0; r < 9; r++)
        g_ctxpart[(((size_t)bh * KCH) + kc) * (U * D) + (ug + 5 * r) * D + d] = acc[r];
}

__global__ __launch_bounds__(256) void ctx_reduce_kernel() {
    int i = blockIdx.x * 256 + threadIdx.x;
    if (i >= BH * U * D) return;
    int bh = i / (U * D), rem = i % (U * D);
    float s = 0.0f;
#pragma unroll
    for (int kc = 0; kc < KCH; kc++)
        s += g_ctxpart[((size_t)bh * KCH + kc) * (U * D) + rem];
    g_ctxsel[i] = s;
}

// ---------------- context = broadcast vmean, then scatter ctx_sel ----------------
__global__ __launch_bounds__(256) void fill_context_kernel() {
    size_t e = (size_t)blockIdx.x * 256 + threadIdx.x;   // < 8388608
    int col = (int)(e & (HD - 1));
    size_t bl = e >> 9;
    int b = (int)(bl >> 12);
    int h = col >> 6, d = col & 63;
    g_context[e] = g_vmean[(b * H + h) * D + d];
}

__global__ __launch_bounds__(64) void scatter_kernel() {
    int bhu = blockIdx.x;              // 0..1439
    int d = threadIdx.x;
    int bh = bhu / U, u = bhu % U;
    int b = bh >> 3, h = bh & 7;
    int li = g_topidx[bh * U + u];
    g_context[((size_t)b * L + li) * HD + h * D + d] = g_ctxsel[(size_t)bhu * D + d];
}

// ---------------- launch ----------------
extern "C" void kernel_launch(void* const* d_in, const int* in_sizes, int n_in,
                              void* d_out, int out_size) {
    const float* x  = (const float*)d_in[0];
    const float* Wq = (const float*)d_in[1];
    const float* Wk = (const float*)d_in[2];
    const float* Wv = (const float*)d_in[3];
    const float* Wo = (const float*)d_in[4];
    const int*   idx = (const int*)d_in[5];
    float* out = (float*)d_out;

    float *Q, *K, *V, *CTX;
    cudaGetSymbolAddress((void**)&Q,   g_Q);
    cudaGetSymbolAddress((void**)&K,   g_K);
    cudaGetSymbolAddress((void**)&V,   g_V);
    cudaGetSymbolAddress((void**)&CTX, g_context);

    dim3 gg(HD / 128, BL / 128);       // (4, 128)
    gemm128<<<gg, 256>>>(x, Wq, Q);
    gemm128<<<gg, 256>>>(x, Wk, K);
    gemm128<<<gg, 256>>>(x, Wv, V);

    vmean_kernel<<<BH, 256>>>();
    compute_M_kernel<<<BL, 256>>>(idx);
    topk_kernel<<<BH, 256>>>();

    scores_kernel<<<dim3(L / 128, BH), 256>>>();
    softmax_kernel<<<BH * U, 256>>>();
    ctx_partial_kernel<<<dim3(KCH, BH), 320>>>();
    ctx_reduce_kernel<<<(BH * U * D + 255) / 256, 256>>>();

    fill_context_kernel<<<(BL * HD) / 256, 256>>>();
    scatter_kernel<<<BH * U, 64>>>();

    gemm128<<<gg, 256>>>(CTX, Wo, out);
}

// round 5
// speedup vs baseline: 2.1376x; 2.1376x over previous
#include <cuda_runtime.h>
#include <cuda_bf16.h>
#include <float.h>
#include <stdint.h>

// Problem constants
#define B   4
#define L   4096
#define HD  512
#define H   8
#define D   64
#define S   45
#define U   45
#define BL  (B * L)            // 16384
#define BH  (B * H)            // 32
#define KCH 8                  // K-split chunks for PV GEMM

// ---------------- device scratch (static; no runtime allocation) ----------------
__device__ __nv_bfloat16 g_x0[BL * HD];
__device__ __nv_bfloat16 g_x1[BL * HD];
__device__ __nv_bfloat16 g_x2[BL * HD];
__device__ __nv_bfloat16 g_W2qk[3072 * 1024];   // 6-term stacked [Wq|Wk]
__device__ __nv_bfloat16 g_W2v[1536 * 512];     // 3-term stacked Wv
__device__ __nv_bfloat16 g_W2o[1536 * 512];     // 3-term stacked Wo
__device__ __nv_bfloat16 g_c0[BL * HD];         // context hi
__device__ __nv_bfloat16 g_c1[BL * HD];         // context lo
__device__ float g_Q[BL * HD];
__device__ float g_K[BL * HD];
__device__ float g_V[BL * HD];
__device__ float g_M[BH * L];
__device__ int   g_topidx[BH * U];
__device__ float g_scores[BH * U * L];
__device__ float g_vmeanpart[BH * 8 * D];
__device__ float g_vmean[BH * D];
__device__ float g_ctxpart[BH * KCH * U * D];
__device__ float g_ctxsel[BH * U * D];

static __device__ __forceinline__ unsigned short bf16u(__nv_bfloat16 v) {
    return *(unsigned short*)&v;
}

// ---------------- split x into 3 bf16 residual levels ----------------
__global__ __launch_bounds__(256) void split_x_kernel(const float* __restrict__ x) {
    size_t i = ((size_t)blockIdx.x * 256 + threadIdx.x) * 4;
    float4 v = *(const float4*)(x + i);
    float vv[4] = {v.x, v.y, v.z, v.w};
    unsigned short h0[4], h1[4], h2[4];
#pragma unroll
    for (int j = 0; j < 4; j++) {
        __nv_bfloat16 b0 = __float2bfloat16_rn(vv[j]);
        float r1 = vv[j] - __bfloat162float(b0);
        __nv_bfloat16 b1 = __float2bfloat16_rn(r1);
        __nv_bfloat16 b2 = __float2bfloat16_rn(r1 - __bfloat162float(b1));
        h0[j] = bf16u(b0); h1[j] = bf16u(b1); h2[j] = bf16u(b2);
    }
    uint2 p;
    p.x = h0[0] | ((uint32_t)h0[1] << 16); p.y = h0[2] | ((uint32_t)h0[3] << 16);
    *(uint2*)&g_x0[i] = p;
    p.x = h1[0] | ((uint32_t)h1[1] << 16); p.y = h1[2] | ((uint32_t)h1[3] << 16);
    *(uint2*)&g_x1[i] = p;
    p.x = h2[0] | ((uint32_t)h2[1] << 16); p.y = h2[2] | ((uint32_t)h2[3] << 16);
    *(uint2*)&g_x2[i] = p;
}

// ---------------- build stacked split-W matrices ----------------
// wsel: 2 bits per 512-row section selecting split level (0/1/2), nsec sections.
__global__ __launch_bounds__(256) void build_w2_kernel(const float* __restrict__ W,
                                                       __nv_bfloat16* __restrict__ out,
                                                       int outW, int colOff,
                                                       int wsel, int nsec) {
    int id = blockIdx.x * 256 + threadIdx.x;   // < 512*512
    int r = id >> 9, c = id & 511;
    float v = W[id];
    __nv_bfloat16 b0 = __float2bfloat16_rn(v);
    float r1 = v - __bfloat162float(b0);
    __nv_bfloat16 b1 = __float2bfloat16_rn(r1);
    __nv_bfloat16 b2 = __float2bfloat16_rn(r1 - __bfloat162float(b1));
    for (int t = 0; t < nsec; t++) {
        int s = (wsel >> (2 * t)) & 3;
        out[(size_t)(t * 512 + r) * outW + colOff + c] = (s == 0) ? b0 : ((s == 1) ? b1 : b2);
    }
}

// ---------------- bf16 split GEMM via mma.sync (HMMA) ----------------
// C[M,*] = sum over stacked-K sections of A_sel @ W2.  128x128 tile, BK=32,
// 256 threads = 8 warps in 2x4 (64x32 warp tiles), double-buffered smem.
__global__ __launch_bounds__(256) void gemm_bf16(
    const __nv_bfloat16* __restrict__ A0, const __nv_bfloat16* __restrict__ A1,
    const __nv_bfloat16* __restrict__ A2,
    const __nv_bfloat16* __restrict__ W2, int Nw, int Ktot, int asel,
    float* __restrict__ o0, float* __restrict__ o1, float* __restrict__ o2)
{
    __shared__ __nv_bfloat16 As[2][128][40];
    __shared__ __nv_bfloat16 Bs[2][32][136];

    int tid = threadIdx.x;
    int warp = tid >> 5, lane = tid & 31;
    int bm = blockIdx.y * 128;
    int bn = blockIdx.x * 128;
    int wm = (warp >> 2) * 64;
    int wn = (warp & 3) * 32;

    float acc[4][4][4];
#pragma unroll
    for (int mi = 0; mi < 4; mi++)
#pragma unroll
        for (int ni = 0; ni < 4; ni++)
#pragma unroll
            for (int r = 0; r < 4; r++) acc[mi][ni][r] = 0.0f;

    int arow0 = tid >> 2;            // 0..63
    int acol0 = (tid & 3) * 8;       // 0,8,16,24
    int brow0 = tid >> 4;            // 0..15
    int bcol0 = (tid & 15) * 8;      // 0..120

    int kiter = Ktot / 32;
    uint4 ra0, ra1, rb0, rb1;

    // prologue: fetch tile 0
    {
        int s = asel & 3;
        const __nv_bfloat16* Asrc = (s == 0) ? A0 : ((s == 1) ? A1 : A2);
        ra0 = *(const uint4*)&Asrc[(size_t)(bm + arow0) * HD + acol0];
        ra1 = *(const uint4*)&Asrc[(size_t)(bm + 64 + arow0) * HD + acol0];
        rb0 = *(const uint4*)&W2[(size_t)brow0 * Nw + bn + bcol0];
        rb1 = *(const uint4*)&W2[(size_t)(16 + brow0) * Nw + bn + bcol0];
        *(uint4*)&As[0][arow0][acol0]      = ra0;
        *(uint4*)&As[0][64 + arow0][acol0] = ra1;
        *(uint4*)&Bs[0][brow0][bcol0]      = rb0;
        *(uint4*)&Bs[0][16 + brow0][bcol0] = rb1;
    }
    __syncthreads();

    int cur = 0;
    for (int it = 0; it < kiter; it++) {
        if (it + 1 < kiter) {
            int kk0 = (it + 1) * 32;
            int s = (asel >> (2 * (kk0 >> 9))) & 3;
            const __nv_bfloat16* Asrc = (s == 0) ? A0 : ((s == 1) ? A1 : A2);
            int scol = kk0 & 511;
            ra0 = *(const uint4*)&Asrc[(size_t)(bm + arow0) * HD + scol + acol0];
            ra1 = *(const uint4*)&Asrc[(size_t)(bm + 64 + arow0) * HD + scol + acol0];
            rb0 = *(const uint4*)&W2[(size_t)(kk0 + brow0) * Nw + bn + bcol0];
            rb1 = *(const uint4*)&W2[(size_t)(kk0 + 16 + brow0) * Nw + bn + bcol0];
        }
#pragma unroll
        for (int ks = 0; ks < 32; ks += 16) {
            uint32_t af[4][4], bfr[4][2];
#pragma unroll
            for (int mi = 0; mi < 4; mi++) {
                uint32_t addr = (uint32_t)__cvta_generic_to_shared(
                    &As[cur][wm + mi * 16 + (lane & 15)][ks + ((lane >> 4) << 3)]);
                asm volatile("ldmatrix.sync.aligned.m8n8.x4.shared.b16 {%0,%1,%2,%3}, [%4];\n"
                             : "=r"(af[mi][0]), "=r"(af[mi][1]), "=r"(af[mi][2]), "=r"(af[mi][3])
                             : "r"(addr));
            }
#pragma unroll
            for (int ni = 0; ni < 4; ni++) {
                uint32_t addr = (uint32_t)__cvta_generic_to_shared(
                    &Bs[cur][ks + (lane & 15)][wn + ni * 8]);
                asm volatile("ldmatrix.sync.aligned.m8n8.x2.trans.shared.b16 {%0,%1}, [%2];\n"
                             : "=r"(bfr[ni][0]), "=r"(bfr[ni][1]) : "r"(addr));
            }
#pragma unroll
            for (int mi = 0; mi < 4; mi++)
#pragma unroll
                for (int ni = 0; ni < 4; ni++) {
                    asm volatile(
                        "mma.sync.aligned.m16n8k16.row.col.f32.bf16.bf16.f32 "
                        "{%0,%1,%2,%3}, {%4,%5,%6,%7}, {%8,%9}, {%0,%1,%2,%3};\n"
                        : "+f"(acc[mi][ni][0]), "+f"(acc[mi][ni][1]),
                          "+f"(acc[mi][ni][2]), "+f"(acc[mi][ni][3])
                        : "r"(af[mi][0]), "r"(af[mi][1]), "r"(af[mi][2]), "r"(af[mi][3]),
                          "r"(bfr[ni][0]), "r"(bfr[ni][1]));
                }
        }
        if (it + 1 < kiter) {
            int nb = cur ^ 1;
            *(uint4*)&As[nb][arow0][acol0]      = ra0;
            *(uint4*)&As[nb][64 + arow0][acol0] = ra1;
            *(uint4*)&Bs[nb][brow0][bcol0]      = rb0;
            *(uint4*)&Bs[nb][16 + brow0][bcol0] = rb1;
            __syncthreads();
            cur ^= 1;
        }
    }

    // epilogue: each 512-wide column section maps to one output buffer
    int sec = bn >> 9;
    float* O = (sec == 0) ? o0 : ((sec == 1) ? o1 : o2);
    int nb0 = bn & 511;
#pragma unroll
    for (int mi = 0; mi < 4; mi++) {
        int r = bm + wm + mi * 16 + (lane >> 2);
#pragma unroll
        for (int ni = 0; ni < 4; ni++) {
            int c = nb0 + wn + ni * 8 + ((lane & 3) << 1);
            float2 v0 = make_float2(acc[mi][ni][0], acc[mi][ni][1]);
            float2 v1 = make_float2(acc[mi][ni][2], acc[mi][ni][3]);
            *(float2*)&O[(size_t)r * HD + c] = v0;
            *(float2*)&O[(size_t)(r + 8) * HD + c] = v1;
        }
    }
}

// ---------------- v mean over L per (b,h,d): partial then reduce ----------------
__global__ __launch_bounds__(256) void vmean_part_kernel() {
    int bh = blockIdx.x & 31, part = blockIdx.x >> 5;    // grid 256
    int b = bh >> 3, h = bh & 7;
    int t = threadIdx.x;
    int d = t & 63, sub = t >> 6;
    const float* base = g_V + (size_t)b * L * HD + h * D + d;
    float s = 0.0f;
    int lend = (part + 1) * 512;
    for (int l = part * 512 + sub; l < lend; l += 4) s += base[(size_t)l * HD];
    __shared__ float sm[256];
    sm[t] = s;
    __syncthreads();
    if (t < 64)
        g_vmeanpart[(bh * 8 + part) * D + t] = sm[t] + sm[t + 64] + sm[t + 128] + sm[t + 192];
}

__global__ __launch_bounds__(256) void vmean_reduce_kernel() {
    int i = blockIdx.x * 256 + threadIdx.x;
    if (i >= BH * D) return;
    int bh = i >> 6, d = i & 63;
    float s = 0.0f;
#pragma unroll
    for (int p = 0; p < 8; p++) s += g_vmeanpart[(bh * 8 + p) * D + d];
    g_vmean[i] = s * (1.0f / (float)L);
}

// ---------------- M[b,h,l] = max_s(qk) - mean_s(qk) ----------------
__global__ __launch_bounds__(256) void compute_M_kernel(const int* __restrict__ idx) {
    int bl = blockIdx.x;
    int b = bl >> 12;
    int l = bl & (L - 1);
    int h = threadIdx.x >> 5;
    int lane = threadIdx.x & 31;

    const float* qrow = g_Q + (size_t)bl * HD + h * D;
    float q0 = qrow[lane];
    float q1 = qrow[lane + 32];

    float mx = -FLT_MAX, sum = 0.0f;
#pragma unroll 1
    for (int s = 0; s < S; s++) {
        int j = idx[l * S + s];
        const float* krow = g_K + ((size_t)b * L + j) * HD + h * D;
        float p = q0 * krow[lane] + q1 * krow[lane + 32];
#pragma unroll
        for (int o = 16; o; o >>= 1) p += __shfl_xor_sync(0xffffffffu, p, o);
        mx = fmaxf(mx, p);
        sum += p;
    }
    if (lane == 0)
        g_M[((size_t)b * H + h) * L + l] = mx - sum * (1.0f / (float)S);
}

// ---------------- top-45 per (b,h), lowest-index tie-break ----------------
__global__ __launch_bounds__(256) void topk_kernel() {
    int bh = blockIdx.x;
    __shared__ float sv[L];
    __shared__ float rv[256];
    __shared__ int   ri[256];
    int t = threadIdx.x;
    const float* Mrow = g_M + (size_t)bh * L;
    for (int i = t; i < L; i += 256) sv[i] = Mrow[i];
    __syncthreads();
    for (int u = 0; u < U; u++) {
        float best = -FLT_MAX;
        int bi = L;
        for (int i = t; i < L; i += 256) {
            float v = sv[i];
            if (v > best) { best = v; bi = i; }
        }
        rv[t] = best; ri[t] = bi;
        __syncthreads();
        for (int s = 128; s; s >>= 1) {
            if (t < s) {
                if (rv[t + s] > rv[t] || (rv[t + s] == rv[t] && ri[t + s] < ri[t])) {
                    rv[t] = rv[t + s]; ri[t] = ri[t + s];
                }
            }
            __syncthreads();
        }
        if (t == 0) {
            g_topidx[bh * U + u] = ri[0];
            sv[ri[0]] = -FLT_MAX;
        }
        __syncthreads();
    }
}

// ---------------- scores[bh,u,l] = (Qr . k_l) / 8 ----------------
__global__ __launch_bounds__(256) void scores_kernel() {
    int bh = blockIdx.y;
    int b = bh >> 3, h = bh & 7;
    int l0 = blockIdx.x * 128;
    __shared__ float Qs[U][65];
    __shared__ float Ks[128][65];
    int t = threadIdx.x;

    for (int i = t; i < U * D; i += 256) {
        int u = i >> 6, d = i & 63;
        int li = g_topidx[bh * U + u];
        Qs[u][d] = g_Q[((size_t)b * L + li) * HD + h * D + d];
    }
    for (int i = t; i < 128 * D; i += 256) {
        int r = i >> 6, d = i & 63;
        Ks[r][d] = g_K[((size_t)b * L + l0 + r) * HD + h * D + d];
    }
    __syncthreads();

    for (int i = t; i < U * 128; i += 256) {
        int u = i >> 7, l = i & 127;
        float acc = 0.0f;
#pragma unroll
        for (int d = 0; d < D; d++) acc += Qs[u][d] * Ks[l][d];
        g_scores[((size_t)bh * U + u) * L + l0 + l] = acc * 0.125f;
    }
}

// ---------------- softmax over L per (bh,u) row; in place ----------------
__global__ __launch_bounds__(256) void softmax_kernel() {
    size_t row = blockIdx.x;
    float* p = g_scores + row * L;
    __shared__ float red[256];
    int t = threadIdx.x;

    float mx = -FLT_MAX;
    for (int i = t; i < L; i += 256) mx = fmaxf(mx, p[i]);
    red[t] = mx;
    __syncthreads();
    for (int s = 128; s; s >>= 1) { if (t < s) red[t] = fmaxf(red[t], red[t + s]); __syncthreads(); }
    mx = red[0];
    __syncthreads();

    float sum = 0.0f;
    for (int i = t; i < L; i += 256) {
        float e = __expf(p[i] - mx);
        p[i] = e;
        sum += e;
    }
    red[t] = sum;
    __syncthreads();
    for (int s = 128; s; s >>= 1) { if (t < s) red[t] += red[t + s]; __syncthreads(); }
    float inv = 1.0f / red[0];
    __syncthreads();
    for (int i = t; i < L; i += 256) p[i] *= inv;
}

// ---------------- PV partial over L chunks ----------------
__global__ __launch_bounds__(320) void ctx_partial_kernel() {
    int kc = blockIdx.x, bh = blockIdx.y;
    int b = bh >> 3, h = bh & 7;
    __shared__ float As[U][65];
    __shared__ float Vs[64][65];
    int t = threadIdx.x;
    int d = t & 63, ug = t >> 6;

    float acc[9];
#pragma unroll
    for (int r = 0; r < 9; r++) acc[r] = 0.0f;

    int lbase = kc * (L / KCH);
    for (int lt = 0; lt < L / KCH; lt += 64) {
        for (int i = t; i < 64 * 64; i += 320) {
            int r = i >> 6, dd = i & 63;
            Vs[r][dd] = g_V[((size_t)b * L + lbase + lt + r) * HD + h * D + dd];
        }
        for (int i = t; i < U * 64; i += 320) {
            int u = i >> 6, ll = i & 63;
            As[u][ll] = g_scores[((size_t)bh * U + u) * L + lbase + lt + ll];
        }
        __syncthreads();
#pragma unroll 8
        for (int ll = 0; ll < 64; ll++) {
            float vv = Vs[ll][d];
#pragma unroll
            for (int r = 0; r < 9; r++) acc[r] += As[ug + 5 * r][ll] * vv;
        }
        __syncthreads();
    }
#pragma unroll
    for (int r = 0; r < 9; r++)
        g_ctxpart[(((size_t)bh * KCH) + kc) * (U * D) + (ug + 5 * r) * D + d] = acc[r];
}

__global__ __launch_bounds__(256) void ctx_reduce_kernel() {
    int i = blockIdx.x * 256 + threadIdx.x;
    if (i >= BH * U * D) return;
    int bh = i / (U * D), rem = i % (U * D);
    float s = 0.0f;
#pragma unroll
    for (int kc = 0; kc < KCH; kc++)
        s += g_ctxpart[((size_t)bh * KCH + kc) * (U * D) + rem];
    g_ctxsel[i] = s;
}

// ---------------- context (bf16 hi/lo) = vmean broadcast + scatter ----------------
__global__ __launch_bounds__(256) void fill_context_kernel() {
    size_t e = (size_t)blockIdx.x * 256 + threadIdx.x;
    int col = (int)(e & (HD - 1));
    size_t bl = e >> 9;
    int b = (int)(bl >> 12);
    int h = col >> 6, d = col & 63;
    float v = g_vmean[(b * H + h) * D + d];
    __nv_bfloat16 hh = __float2bfloat16_rn(v);
    g_c0[e] = hh;
    g_c1[e] = __float2bfloat16_rn(v - __bfloat162float(hh));
}

__global__ __launch_bounds__(64) void scatter_kernel() {
    int bhu = blockIdx.x;
    int d = threadIdx.x;
    int bh = bhu / U, u = bhu % U;
    int b = bh >> 3, h = bh & 7;
    int li = g_topidx[bh * U + u];
    float v = g_ctxsel[(size_t)bhu * D + d];
    __nv_bfloat16 hh = __float2bfloat16_rn(v);
    size_t e = ((size_t)b * L + li) * HD + h * D + d;
    g_c0[e] = hh;
    g_c1[e] = __float2bfloat16_rn(v - __bfloat162float(hh));
}

// ---------------- launch ----------------
extern "C" void kernel_launch(void* const* d_in, const int* in_sizes, int n_in,
                              void* d_out, int out_size) {
    const float* x  = (const float*)d_in[0];
    const float* Wq = (const float*)d_in[1];
    const float* Wk = (const float*)d_in[2];
    const float* Wv = (const float*)d_in[3];
    const float* Wo = (const float*)d_in[4];
    const int*   idx = (const int*)d_in[5];
    float* out = (float*)d_out;

    __nv_bfloat16 *x0, *x1, *x2, *W2qk, *W2v, *W2o, *c0, *c1;
    float *Q, *K, *V;
    cudaGetSymbolAddress((void**)&x0, g_x0);
    cudaGetSymbolAddress((void**)&x1, g_x1);
    cudaGetSymbolAddress((void**)&x2, g_x2);
    cudaGetSymbolAddress((void**)&W2qk, g_W2qk);
    cudaGetSymbolAddress((void**)&W2v,  g_W2v);
    cudaGetSymbolAddress((void**)&W2o,  g_W2o);
    cudaGetSymbolAddress((void**)&c0, g_c0);
    cudaGetSymbolAddress((void**)&c1, g_c1);
    cudaGetSymbolAddress((void**)&Q, g_Q);
    cudaGetSymbolAddress((void**)&K, g_K);
    cudaGetSymbolAddress((void**)&V, g_V);

    // split inputs
    split_x_kernel<<<(BL * HD) / 1024, 256>>>(x);
    // 6-term map: sections A{0,0,1,0,1,2} W{0,1,0,2,1,0}
    build_w2_kernel<<<1024, 256>>>(Wq, W2qk, 1024, 0,   0x184, 6);
    build_w2_kernel<<<1024, 256>>>(Wk, W2qk, 1024, 512, 0x184, 6);
    // 3-term map: A{0,0,1} W{0,1,0}
    build_w2_kernel<<<1024, 256>>>(Wv, W2v, 512, 0, 0x4, 3);
    build_w2_kernel<<<1024, 256>>>(Wo, W2o, 512, 0, 0x4, 3);

    // Q,K projection: 6-term (asel packed 2b/section: {0,0,1,0,1,2} -> 0x910)
    gemm_bf16<<<dim3(8, 128), 256>>>(x0, x1, x2, W2qk, 1024, 3072, 0x910, Q, K, K);
    // V projection: 3-term (asel {0,0,1} -> 0x10)
    gemm_bf16<<<dim3(4, 128), 256>>>(x0, x1, x2, W2v, 512, 1536, 0x10, V, V, V);

    vmean_part_kernel<<<256, 256>>>();
    vmean_reduce_kernel<<<8, 256>>>();
    compute_M_kernel<<<BL, 256>>>(idx);
    topk_kernel<<<BH, 256>>>();

    scores_kernel<<<dim3(L / 128, BH), 256>>>();
    softmax_kernel<<<BH * U, 256>>>();
    ctx_partial_kernel<<<dim3(KCH, BH), 320>>>();
    ctx_reduce_kernel<<<(BH * U * D + 255) / 256, 256>>>();

    fill_context_kernel<<<(BL * HD) / 256, 256>>>();
    scatter_kernel<<<BH * U, 64>>>();

    // output projection: 3-term on context hi/lo
    gemm_bf16<<<dim3(4, 128), 256>>>(c0, c1, c1, W2o, 512, 1536, 0x10, out, out, out);
}